// round 13
// baseline (speedup 1.0000x reference)
#include <cuda_runtime.h>
#include <math.h>

#define BB 8
#define LL 2048
#define KSEL 64
#define GRP 8            // rows per item == warps per block
#define NBINS 256
#define THREADS 256
#define NITEMS (BB * LL / GRP)    // 2048 work items (8 rows each)
#define IPB (LL / GRP)            // 256 items per batch
#define GRID 592                  // 148 SMs x 4 blocks
#define POOLCAP 4096

// scratch (no cudaMalloc allowed)
__device__ float g_itemsum[NITEMS];
__device__ unsigned int g_work = 0;
__device__ unsigned int g_done = 0;

// dynamic smem: pts (32KB) + candidate pool (8KB) + per-row hist (8KB)
#define SM_PTS_BYTES  (LL * 16)
#define SM_POOL_BYTES (POOLCAP * 2)
#define SM_HIST_BYTES (GRP * NBINS * 4)
#define SM_DYN_BYTES  (SM_PTS_BYTES + SM_POOL_BYTES + SM_HIST_BYTES)  // 49152

typedef unsigned long long u64;

__device__ __forceinline__ u64 pack2(float lo, float hi) {
    u64 r; asm("mov.b64 %0,{%1,%2};" : "=l"(r) : "f"(lo), "f"(hi)); return r;
}
__device__ __forceinline__ u64 add2(u64 a, u64 b) {
    u64 r; asm("add.rn.f32x2 %0,%1,%2;" : "=l"(r) : "l"(a), "l"(b)); return r;
}
__device__ __forceinline__ u64 fma2(u64 a, u64 b, u64 c) {
    u64 r; asm("fma.rn.f32x2 %0,%1,%2,%3;" : "=l"(r) : "l"(a), "l"(b), "l"(c)); return r;
}
__device__ __forceinline__ void unpack2(u64 v, unsigned &lo, unsigned &hi) {
    asm("mov.b64 {%0,%1},%2;" : "=r"(lo), "=r"(hi) : "l"(v));
}

__device__ __forceinline__ float dist2(float4 a, float4 b) {
    float dx = a.x - b.x, dy = a.y - b.y, dz = a.z - b.z;
    return fmaf(dx, dx, fmaf(dy, dy, dz * dz));
}

__device__ __forceinline__ float contrib(float d2, float r0) {
    float r = sqrtf(fmaxf(d2, 1e-12f));
    float x = (r0 - r) * (1.0f / 0.3f);                       // (r0-r)/DELTA
    float sp = fmaxf(x, 0.0f) + log1pf(expf(-fabsf(x)));      // stable softplus
    float t = fminf(fmaxf((r - 8.0f) * 0.5f, 0.0f), 1.0f);    // smooth switch
    float sw = 1.0f - t * t * (3.0f - 2.0f * t);
    return 10.0f * sp * sw;                                   // WALL * sp * sw
}

__global__ void __launch_bounds__(THREADS, 4)
main_kernel(const float* __restrict__ R,
            const void*  __restrict__ seq,
            const float* __restrict__ emb,
            const float* __restrict__ wv,
            const float* __restrict__ bp,
            float* __restrict__ out) {
    extern __shared__ char smem[];
    float4*         s_pts  = (float4*)smem;
    unsigned short* s_pool = (unsigned short*)(smem + SM_PTS_BYTES);
    int*            s_hist = (int*)(smem + SM_PTS_BYTES + SM_POOL_BYTES);

    __shared__ float s_dotv[20];
    __shared__ int   s_tb[GRP], s_mm[GRP], s_bcnt[GRP];
    __shared__ float s_bnd_d2[GRP][64];
    __shared__ unsigned short s_bnd_j[GRP][64];
    __shared__ float s_wsum[GRP];
    __shared__ int   s_flag64, s_last, s_poolcnt, s_item;

    const int tid  = threadIdx.x;
    const int lane = tid & 31;
    const int wid  = tid >> 5;

    // ---- dot(emb[s], w) + b LUT, int64-vs-int32 seq detection ----
    if (tid == 0) s_flag64 = 1;
    if (tid < 20) {
        float x = bp[0];
#pragma unroll
        for (int d = 0; d < 16; d++) x = fmaf(emb[tid * 16 + d], wv[d], x);
        s_dotv[tid] = x;
    }
    __syncthreads();
    if (tid < 64 && ((const int*)seq)[2 * tid + 1] != 0) s_flag64 = 0;
    __syncthreads();
    const bool is64 = (s_flag64 != 0);

    const u64 C100 = pack2(-100.0f, -100.0f);
    int cur_b = -1;

    // ---- persistent loop over dynamic 8-row work items ----
    while (true) {
        if (tid == 0) s_item = (int)atomicAdd(&g_work, 1u);
        __syncthreads();                  // broadcast item; protect prev smem
        const int item = s_item;
        if (item >= NITEMS) break;
        const int b  = item >> 8;         // IPB == 256
        const int i0 = (item & (IPB - 1)) * GRP;

        if (b != cur_b) {
            const float* Rb = R + (size_t)b * LL * 3;
            for (int j = tid; j < LL; j += THREADS) {
                int s;
                if (is64) s = (int)((const long long*)seq)[(size_t)b * LL + j];
                else      s = ((const int*)seq)[b * LL + j];
                float x = s_dotv[s];
                float rho = 1.6f + 1.2f / (1.0f + expf(-x));
                s_pts[j] = make_float4(Rb[j * 3 + 0], Rb[j * 3 + 1], Rb[j * 3 + 2], rho);
            }
            cur_b = b;
        }

        if (tid == 0) s_poolcnt = 0;
        if (tid < GRP) s_bcnt[tid] = 0;
#pragma unroll
        for (int k = 0; k < (GRP * NBINS) / THREADS; k++)
            s_hist[k * THREADS + tid] = 0;
        __syncthreads();                  // pts + zeroing visible

        float lsum = 0.0f;

        // negated row-pair broadcasts: lane lo = row 2rp, lane hi = row 2rp+1
        u64 nx2[4], ny2[4], nz2[4];
#pragma unroll
        for (int rp = 0; rp < 4; rp++) {
            float4 a  = s_pts[i0 + 2 * rp];
            float4 b2 = s_pts[i0 + 2 * rp + 1];
            nx2[rp] = pack2(-a.x, -b2.x);
            ny2[rp] = pack2(-a.y, -b2.y);
            nz2[rp] = pack2(-a.z, -b2.z);
        }

        // ---- pass 1: packed f32x2 distances, sign-bit filter, pool append ----
#pragma unroll
        for (int jj = 0; jj < LL / (2 * THREADS); jj++) {
            int j  = jj * (2 * THREADS) + tid;
            int j2 = j + THREADS;
            float4 p1 = s_pts[j];
            float4 p2 = s_pts[j2];
            u64 p1x = pack2(p1.x, p1.x), p1y = pack2(p1.y, p1.y), p1z = pack2(p1.z, p1.z);
            u64 p2x = pack2(p2.x, p2.x), p2y = pack2(p2.y, p2.y), p2z = pack2(p2.z, p2.z);
            unsigned mask = 0;
#pragma unroll
            for (int rp = 0; rp < 4; rp++) {
                u64 dx = add2(p1x, nx2[rp]);
                u64 dy = add2(p1y, ny2[rp]);
                u64 dz = add2(p1z, nz2[rp]);
                u64 t  = fma2(dz, dz, C100);
                t = fma2(dy, dy, t);
                t = fma2(dx, dx, t);               // d2 - 100 per half
                unsigned lo, hi; unpack2(t, lo, hi);
                mask |= (lo >> 31) << (2 * rp);
                mask |= (hi >> 31) << (2 * rp + 1);

                dx = add2(p2x, nx2[rp]);
                dy = add2(p2y, ny2[rp]);
                dz = add2(p2z, nz2[rp]);
                t  = fma2(dz, dz, C100);
                t = fma2(dy, dy, t);
                t = fma2(dx, dx, t);
                unpack2(t, lo, hi);
                mask |= (lo >> 31) << (8 + 2 * rp);
                mask |= (hi >> 31) << (8 + 2 * rp + 1);
            }
            // bonded-exclusion windows (rare)
            int rel = j - i0;
            if ((unsigned)(rel + 2) < 12u) {
                int lo = rel - 2; unsigned m = 0x1Fu;
                if (lo < 0) { m >>= -lo; lo = 0; }
                mask &= ~((m << lo) & 0xFFu);
            }
            int rel2 = j2 - i0;
            if ((unsigned)(rel2 + 2) < 12u) {
                int lo = rel2 - 2; unsigned m = 0x1Fu;
                if (lo < 0) { m >>= -lo; lo = 0; }
                mask &= ~(((m << lo) & 0xFFu) << 8);
            }

            int cnt = __popc(mask);
            int scan = cnt;
#pragma unroll
            for (int off = 1; off < 32; off <<= 1) {
                int v = __shfl_up_sync(0xffffffffu, scan, off);
                if (lane >= off) scan += v;
            }
            int base = 0;
            if (lane == 31) base = atomicAdd(&s_poolcnt, scan);
            base = __shfl_sync(0xffffffffu, base, 31) + scan - cnt;
            unsigned mm2 = mask;
            while (mm2) {
                int bpos = __ffs(mm2) - 1;
                mm2 &= mm2 - 1;
                int k  = bpos & 7;
                int jx = (bpos & 8) ? j2 : j;
                if (base < POOLCAP)
                    s_pool[base] = (unsigned short)((jx << 3) | k);
                base++;
            }
        }
        __syncthreads();

        int cnt_all = s_poolcnt; if (cnt_all > POOLCAP) cnt_all = POOLCAP;

        // ---- histogram over pool ----
        for (int e = tid; e < cnt_all; e += THREADS) {
            int rec = s_pool[e];
            int k = rec & 7, j = rec >> 3;
            float d2 = dist2(s_pts[i0 + k], s_pts[j]);
            int bin = (int)(d2 * 2.56f); if (bin > 255) bin = 255;
            atomicAdd(&s_hist[k * NBINS + bin], 1);
        }
        __syncthreads();

        // ---- threshold scan: warp w -> row w ----
        {
            int* hist = s_hist + wid * NBINS;
            int loc[8]; int ssum = 0;
#pragma unroll
            for (int k = 0; k < 8; k++) { loc[k] = hist[lane * 8 + k]; ssum += loc[k]; }
            int scan = ssum;
#pragma unroll
            for (int off = 1; off < 32; off <<= 1) {
                int v = __shfl_up_sync(0xffffffffu, scan, off);
                if (lane >= off) scan += v;
            }
            int total  = __shfl_sync(0xffffffffu, scan, 31);
            int before = scan - ssum;
            bool own = (total > KSEL) && (before < KSEL) && (scan >= KSEL);
            int tb = NBINS, mm = 0;
            if (own) {
                int cum = before;
#pragma unroll
                for (int k = 0; k < 8; k++) {
                    if (cum + loc[k] >= KSEL) { tb = lane * 8 + k; mm = KSEL - cum; break; }
                    cum += loc[k];
                }
            }
            unsigned omsk = __ballot_sync(0xffffffffu, own);
            if (omsk) {
                int src = __ffs(omsk) - 1;
                tb = __shfl_sync(0xffffffffu, tb, src);
                mm = __shfl_sync(0xffffffffu, mm, src);
            }
            if (lane == 0) { s_tb[wid] = tb; s_mm[wid] = mm; }
        }
        __syncthreads();

        // ---- accumulate over pool; collect boundary candidates ----
        for (int e = tid; e < cnt_all; e += THREADS) {
            int rec = s_pool[e];
            int k = rec & 7, j = rec >> 3;
            float4 pi = s_pts[i0 + k];
            float4 pj = s_pts[j];
            float d2 = dist2(pi, pj);
            int bin = (int)(d2 * 2.56f); if (bin > 255) bin = 255;
            int tb = s_tb[k];
            if (bin < tb) {
                lsum += contrib(d2, pi.w + pj.w);
            } else if (bin == tb) {
                int pos = atomicAdd(&s_bcnt[k], 1);
                if (pos < 64) {
                    s_bnd_d2[k][pos] = d2;
                    s_bnd_j[k][pos] = (unsigned short)j;
                }
            }
        }
        __syncthreads();

        // ---- boundary rank-select: warp w -> row w (tiny) ----
        {
            int bcnt = s_bcnt[wid]; if (bcnt > 64) bcnt = 64;
            int mm = s_mm[wid];
            float riw = s_pts[i0 + wid].w;
            for (int e = lane; e < bcnt; e += 32) {
                float dk = s_bnd_d2[wid][e]; int jk = s_bnd_j[wid][e];
                int rank = 0;
                for (int l = 0; l < bcnt; l++) {
                    float dl = s_bnd_d2[wid][l];
                    rank += (dl < dk) || (dl == dk && s_bnd_j[wid][l] < jk);
                }
                if (rank < mm) lsum += contrib(dk, riw + s_pts[jk].w);
            }
        }

        // ---- per-item deterministic block reduction -> g_itemsum ----
#pragma unroll
        for (int off = 16; off; off >>= 1) lsum += __shfl_down_sync(0xffffffffu, lsum, off);
        if (lane == 0) s_wsum[wid] = lsum;
        __syncthreads();
        if (tid == 0) {
            float bs = 0.0f;
#pragma unroll
            for (int w2 = 0; w2 < GRP; w2++) bs += s_wsum[w2];
            g_itemsum[item] = bs;
        }
    }

    // ---- completion ticket ----
    __threadfence();
    if (tid == 0) {
        unsigned t = atomicAdd(&g_done, 1u);
        s_last = (t == GRID - 1);
    }
    __syncthreads();

    // ---- last block: per-batch reduce in fixed order (deterministic) ----
    if (s_last) {
        __threadfence();
        volatile float* vi = g_itemsum;
        float s = 0.0f;
#pragma unroll
        for (int e = 0; e < IPB / 32; e++) s += vi[wid * IPB + e * 32 + lane];
#pragma unroll
        for (int off = 16; off; off >>= 1) s += __shfl_down_sync(0xffffffffu, s, off);
        if (lane == 0) out[wid] = s;
        __syncthreads();
        if (tid == 0) { g_work = 0; g_done = 0; }   // reset for graph replay
    }
}

extern "C" void kernel_launch(void* const* d_in, const int* in_sizes, int n_in,
                              void* d_out, int out_size) {
    const float* R   = (const float*)d_in[0];
    const void*  seq = d_in[1];
    const float* emb = (const float*)d_in[2];
    const float* w   = (const float*)d_in[3];
    const float* bp  = (const float*)d_in[4];
    float* out = (float*)d_out;

    static int attr_set = 0;
    if (!attr_set) {
        cudaFuncSetAttribute(main_kernel,
                             cudaFuncAttributeMaxDynamicSharedMemorySize,
                             SM_DYN_BYTES);
        attr_set = 1;
    }
    main_kernel<<<GRID, THREADS, SM_DYN_BYTES>>>(R, seq, emb, w, bp, out);
}